// round 4
// baseline (speedup 1.0000x reference)
#include <cuda_runtime.h>

// Problem constants (fixed by the dataset)
#define BATCH  4096
#define TT     1000
#define HID    32
#define HH     15    // padded to 16 in shared
#define OUTD   8
#define INITD  16

#define NBLK   128   // blocks
#define NTHR   128   // threads per block -> 32 elements/block, 4 threads/element

__device__ __forceinline__ float ftanh(float x) {
    // (e^{2x}-1)/(e^{2x}+1), clamped to avoid overflow; rel err ~1e-6
    x = fminf(fmaxf(x, -15.f), 15.f);
    float e = __expf(2.f * x);
    return __fdividef(e - 1.f, e + 1.f);
}

// dot over 32 inputs (8 float4 weight loads), v is a register array
__device__ __forceinline__ float dot32(const float* __restrict__ row,
                                       const float (&v)[HID], float acc) {
#pragma unroll
    for (int k4 = 0; k4 < 8; k4++) {
        float4 w = *(const float4*)(row + 4 * k4);
        acc = fmaf(v[4 * k4 + 0], w.x, acc);
        acc = fmaf(v[4 * k4 + 1], w.y, acc);
        acc = fmaf(v[4 * k4 + 2], w.z, acc);
        acc = fmaf(v[4 * k4 + 3], w.w, acc);
    }
    return acc;
}

// dot over 16 inputs (4 float4 weight loads)
__device__ __forceinline__ float dot16(const float* __restrict__ row,
                                       const float (&v)[16], float acc) {
#pragma unroll
    for (int k4 = 0; k4 < 4; k4++) {
        float4 w = *(const float4*)(row + 4 * k4);
        acc = fmaf(v[4 * k4 + 0], w.x, acc);
        acc = fmaf(v[4 * k4 + 1], w.y, acc);
        acc = fmaf(v[4 * k4 + 2], w.z, acc);
        acc = fmaf(v[4 * k4 + 3], w.w, acc);
    }
    return acc;
}

__global__ void __launch_bounds__(NTHR, 1) node_kernel(
    const float* __restrict__ times, const float* __restrict__ initial,
    const float* __restrict__ Wi,  const float* __restrict__ bi,
    const float* __restrict__ Wf0, const float* __restrict__ bf0,
    const float* __restrict__ Wf1, const float* __restrict__ bf1,
    const float* __restrict__ Wf2, const float* __restrict__ bf2,
    const float* __restrict__ Wf3, const float* __restrict__ bf3,
    const float* __restrict__ Wl,  const float* __restrict__ bl,
    float* __restrict__ out)
{
    // Transposed weights in shared. Row strides chosen so the 4 roles
    // (rows differing by 1) hit distinct 16B bank columns:
    //   stride 36 floats (144B): offsets {0,16,32,48} mod 128  -> conflict-free
    //   stride 20 floats (80B):  offsets {0,80,32,112} mod 128 -> conflict-free
    __shared__ __align__(16) float sW0[16][36];  // [j][k], j<15 real, k<32
    __shared__ __align__(16) float sW1[16][20];  // [j][k], j<15, k<15 (padded)
    __shared__ __align__(16) float sW2[16][20];
    __shared__ __align__(16) float sW3[32][20];  // [c][k], c<32, k<15 (padded)
    __shared__ __align__(16) float sWl[8][36];   // [o][k], o<8, k<32
    __shared__ float sWi[INITD][HID];            // [k][c]
    __shared__ float sB0[16], sB1[16], sB2[16], sB3[HID], sBl[OUTD];
    __shared__ float sDt[TT - 1];

    const int tid = threadIdx.x;

    // ---- zero padded weight arrays, then fill ----
    for (int i = tid; i < 16 * 36; i += NTHR) (&sW0[0][0])[i] = 0.f;
    for (int i = tid; i < 16 * 20; i += NTHR) { (&sW1[0][0])[i] = 0.f; (&sW2[0][0])[i] = 0.f; }
    for (int i = tid; i < 32 * 20; i += NTHR) (&sW3[0][0])[i] = 0.f;
    for (int i = tid; i <  8 * 36; i += NTHR) (&sWl[0][0])[i] = 0.f;
    __syncthreads();

    for (int i = tid; i < HID * HH; i += NTHR) { int k = i / HH,  j = i % HH;  sW0[j][k] = Wf0[i]; }
    for (int i = tid; i < HH * HH;  i += NTHR) { int k = i / HH,  j = i % HH;  sW1[j][k] = Wf1[i]; sW2[j][k] = Wf2[i]; }
    for (int i = tid; i < HH * HID; i += NTHR) { int k = i / HID, c = i % HID; sW3[c][k] = Wf3[i]; }
    for (int i = tid; i < HID * OUTD; i += NTHR) { int k = i / OUTD, o = i % OUTD; sWl[o][k] = Wl[i]; }
    for (int i = tid; i < INITD * HID; i += NTHR) (&sWi[0][0])[i] = Wi[i];
    if (tid < 16) {
        sB0[tid] = (tid < HH) ? bf0[tid] : 0.f;
        sB1[tid] = (tid < HH) ? bf1[tid] : 0.f;
        sB2[tid] = (tid < HH) ? bf2[tid] : 0.f;
    }
    if (tid < HID)  sB3[tid] = bf3[tid];
    if (tid < OUTD) sBl[tid] = bl[tid];
    for (int t = tid; t < TT - 1; t += NTHR) sDt[t] = times[t + 1] - times[t];
    __syncthreads();

    // ---- thread mapping: 4 consecutive lanes = one batch element ----
    const int e = blockIdx.x * (NTHR / 4) + (tid >> 2);
    const int r = tid & 3;                   // role 0..3
    const unsigned FULL = 0xffffffffu;

    // ---- h0 = initial @ Wi + bi  (replicated across the 4 roles) ----
    float h[HID];
    {
        float x[INITD];
#pragma unroll
        for (int k = 0; k < INITD; k++) x[k] = initial[e * INITD + k];
#pragma unroll
        for (int c = 0; c < HID; c++) {
            float a = bi[c];
#pragma unroll
            for (int k = 0; k < INITD; k++) a = fmaf(x[k], sWi[k][c], a);
            h[c] = a;
        }
    }

    float* __restrict__ oute = out + (size_t)e * TT * OUTD;

    // inline projection: role r writes outputs o = r and o = r+4
    auto project = [&](int t) {
        float y0 = sBl[r], y1 = sBl[r + 4];
        y0 = dot32(&sWl[r][0],     h, y0);
        y1 = dot32(&sWl[r + 4][0], h, y1);
        oute[(size_t)t * OUTD + r]     = y0;
        oute[(size_t)t * OUTD + r + 4] = y1;
    };

    project(0);

    for (int t = 0; t < TT - 1; t++) {
        const float dt = sDt[t];

        // ---- layer 0: 32 -> 15(16), role r owns outputs j = 4*jj + r ----
        float a0 = dot32(&sW0[0  + r][0], h, sB0[0  + r]);
        float a1 = dot32(&sW0[4  + r][0], h, sB0[4  + r]);
        float a2 = dot32(&sW0[8  + r][0], h, sB0[8  + r]);
        float a3 = dot32(&sW0[12 + r][0], h, sB0[12 + r]);
        a0 = ftanh(a0); a1 = ftanh(a1); a2 = ftanh(a2); a3 = ftanh(a3);

        float z[16];
#pragma unroll
        for (int s = 0; s < 4; s++) {
            z[0  + s] = __shfl_sync(FULL, a0, s, 4);
            z[4  + s] = __shfl_sync(FULL, a1, s, 4);
            z[8  + s] = __shfl_sync(FULL, a2, s, 4);
            z[12 + s] = __shfl_sync(FULL, a3, s, 4);
        }

        // ---- layer 1: 15(16) -> 15(16) ----
        a0 = ftanh(dot16(&sW1[0  + r][0], z, sB1[0  + r]));
        a1 = ftanh(dot16(&sW1[4  + r][0], z, sB1[4  + r]));
        a2 = ftanh(dot16(&sW1[8  + r][0], z, sB1[8  + r]));
        a3 = ftanh(dot16(&sW1[12 + r][0], z, sB1[12 + r]));
        float zb[16];
#pragma unroll
        for (int s = 0; s < 4; s++) {
            zb[0  + s] = __shfl_sync(FULL, a0, s, 4);
            zb[4  + s] = __shfl_sync(FULL, a1, s, 4);
            zb[8  + s] = __shfl_sync(FULL, a2, s, 4);
            zb[12 + s] = __shfl_sync(FULL, a3, s, 4);
        }

        // ---- layer 2: 15(16) -> 15(16) ----
        a0 = ftanh(dot16(&sW2[0  + r][0], zb, sB2[0  + r]));
        a1 = ftanh(dot16(&sW2[4  + r][0], zb, sB2[4  + r]));
        a2 = ftanh(dot16(&sW2[8  + r][0], zb, sB2[8  + r]));
        a3 = ftanh(dot16(&sW2[12 + r][0], zb, sB2[12 + r]));
        float zc[16];
#pragma unroll
        for (int s = 0; s < 4; s++) {
            zc[0  + s] = __shfl_sync(FULL, a0, s, 4);
            zc[4  + s] = __shfl_sync(FULL, a1, s, 4);
            zc[8  + s] = __shfl_sync(FULL, a2, s, 4);
            zc[12 + s] = __shfl_sync(FULL, a3, s, 4);
        }

        // ---- layer 3: 15(16) -> 32, role r owns outputs c = 4*cc + r ----
        float f[8];
#pragma unroll
        for (int cc = 0; cc < 8; cc++)
            f[cc] = dot16(&sW3[4 * cc + r][0], zc, sB3[4 * cc + r]);

        // ---- h += dt * f  (all-gather f across the 4 roles) ----
#pragma unroll
        for (int cc = 0; cc < 8; cc++) {
#pragma unroll
            for (int s = 0; s < 4; s++) {
                h[4 * cc + s] = fmaf(dt, __shfl_sync(FULL, f[cc], s, 4),
                                     h[4 * cc + s]);
            }
        }

        project(t + 1);
    }
}

extern "C" void kernel_launch(void* const* d_in, const int* in_sizes, int n_in,
                              void* d_out, int out_size) {
    const float* times   = (const float*)d_in[0];
    const float* initial = (const float*)d_in[1];
    const float* Wi  = (const float*)d_in[2];
    const float* bi  = (const float*)d_in[3];
    const float* Wf0 = (const float*)d_in[4];
    const float* bf0 = (const float*)d_in[5];
    const float* Wf1 = (const float*)d_in[6];
    const float* bf1 = (const float*)d_in[7];
    const float* Wf2 = (const float*)d_in[8];
    const float* bf2 = (const float*)d_in[9];
    const float* Wf3 = (const float*)d_in[10];
    const float* bf3 = (const float*)d_in[11];
    const float* Wl  = (const float*)d_in[12];
    const float* bl  = (const float*)d_in[13];
    float* out = (float*)d_out;

    node_kernel<<<NBLK, NTHR>>>(times, initial, Wi, bi,
                                Wf0, bf0, Wf1, bf1, Wf2, bf2, Wf3, bf3,
                                Wl, bl, out);
}

// round 8
// speedup vs baseline: 1.4559x; 1.4559x over previous
#include <cuda_runtime.h>

// Problem constants (fixed by the dataset)
#define BATCH  4096
#define TT     1000
#define HID    32
#define HH     15    // padded to 16
#define OUTD   8
#define INITD  16

#define NTHR   128                    // threads per block
#define EPB    (NTHR / 8)             // 16 elements per block (8 threads/element)
#define NBLK   (BATCH / EPB)          // 256 blocks -> 1024 warps ~ 2/SMSP

typedef unsigned long long u64;

__device__ __forceinline__ u64 pack2(float x, float y) {
    u64 r; asm("mov.b64 %0, {%1,%2};" : "=l"(r) : "f"(x), "f"(y)); return r;
}
__device__ __forceinline__ float2 unpack2(u64 v) {
    float2 p; asm("mov.b64 {%0,%1}, %2;" : "=f"(p.x), "=f"(p.y) : "l"(v)); return p;
}
// Packed f32x2 FMA / ADD (sm_100+; ptxas will not auto-fuse these)
__device__ __forceinline__ u64 fma2(u64 a, u64 b, u64 c) {
    u64 d; asm("fma.rn.f32x2 %0, %1, %2, %3;" : "=l"(d) : "l"(a), "l"(b), "l"(c)); return d;
}
__device__ __forceinline__ u64 add2(u64 a, u64 b) {
    u64 d; asm("add.rn.f32x2 %0, %1, %2;" : "=l"(d) : "l"(a), "l"(b)); return d;
}

__device__ __forceinline__ float ftanh(float x) {
    x = fminf(fmaxf(x, -15.f), 15.f);
    float e = __expf(2.f * x);
    return __fdividef(e - 1.f, e + 1.f);
}

// dot over 32 inputs: v = 16 packed k-pairs, weights = contiguous 32-float row
__device__ __forceinline__ float dot32p(const float* __restrict__ row,
                                        const u64 (&v)[16], float bias) {
    u64 acc0 = pack2(bias, 0.f);
    u64 acc1 = pack2(0.f, 0.f);
#pragma unroll
    for (int kk = 0; kk < 8; kk++) {
        ulonglong2 w = *(const ulonglong2*)(row + 4 * kk);  // 4 floats = 2 k-pairs
        acc0 = fma2(v[2 * kk + 0], w.x, acc0);
        acc1 = fma2(v[2 * kk + 1], w.y, acc1);
    }
    float2 s = unpack2(add2(acc0, acc1));
    return s.x + s.y;
}

// dot over 16 inputs: v = 8 packed k-pairs, weights = contiguous 16-float row
__device__ __forceinline__ float dot16p(const float* __restrict__ row,
                                        const u64 (&v)[8], float bias) {
    u64 acc0 = pack2(bias, 0.f);
    u64 acc1 = pack2(0.f, 0.f);
#pragma unroll
    for (int kk = 0; kk < 4; kk++) {
        ulonglong2 w = *(const ulonglong2*)(row + 4 * kk);
        acc0 = fma2(v[2 * kk + 0], w.x, acc0);
        acc1 = fma2(v[2 * kk + 1], w.y, acc1);
    }
    float2 s = unpack2(add2(acc0, acc1));
    return s.x + s.y;
}

__global__ void __launch_bounds__(NTHR) node_kernel(
    const float* __restrict__ times, const float* __restrict__ initial,
    const float* __restrict__ Wi,  const float* __restrict__ bi,
    const float* __restrict__ Wf0, const float* __restrict__ bf0,
    const float* __restrict__ Wf1, const float* __restrict__ bf1,
    const float* __restrict__ Wf2, const float* __restrict__ bf2,
    const float* __restrict__ Wf3, const float* __restrict__ bf3,
    const float* __restrict__ Wl,  const float* __restrict__ bl,
    float* __restrict__ out)
{
    // Transposed weights, even/odd output rows in separate arrays.
    // Row strides (in floats): 36 (144B) and 20 (80B) ->
    //   lanes r=0..7 read base + r*stride: offsets mod 128B are all distinct
    //   (144: {0,16,..,112}; 80: {0,80,32,112,64,16,96,48}) -> conflict-free LDS.128.
    __shared__ __align__(16) float sW0e[8][36],  sW0o[8][36];   // rows 2r / 2r+1, k<32
    __shared__ __align__(16) float sW1e[8][20],  sW1o[8][20];   // k<16 (15 + pad)
    __shared__ __align__(16) float sW2e[8][20],  sW2o[8][20];
    __shared__ __align__(16) float sW3e[16][20], sW3o[16][20];  // rows 2c / 2c+1, c<16
    __shared__ __align__(16) float sWl[8][36];                  // [o][k], k<32
    __shared__ __align__(16) float sWi[INITD][HID];
    __shared__ float sB0[16], sB1[16], sB2[16], sB3[HID], sBl[OUTD];
    __shared__ float sDt[TT - 1];

    const int tid = threadIdx.x;

    // ---- zero the padded arrays that get loaded (pads must read 0) ----
    for (int i = tid; i < 8 * 36; i += NTHR) { (&sW0e[0][0])[i] = 0.f; (&sW0o[0][0])[i] = 0.f; }
    for (int i = tid; i < 8 * 20; i += NTHR) {
        (&sW1e[0][0])[i] = 0.f; (&sW1o[0][0])[i] = 0.f;
        (&sW2e[0][0])[i] = 0.f; (&sW2o[0][0])[i] = 0.f;
    }
    for (int i = tid; i < 16 * 20; i += NTHR) { (&sW3e[0][0])[i] = 0.f; (&sW3o[0][0])[i] = 0.f; }
    __syncthreads();

    // ---- fill transposed weights ----
    for (int i = tid; i < HID * HH; i += NTHR) {          // Wf0 [32][15]
        int k = i / HH, j = i % HH; float w = Wf0[i];
        if (j & 1) sW0o[j >> 1][k] = w; else sW0e[j >> 1][k] = w;
    }
    for (int i = tid; i < HH * HH; i += NTHR) {           // Wf1/Wf2 [15][15]
        int k = i / HH, j = i % HH;
        if (j & 1) { sW1o[j >> 1][k] = Wf1[i]; sW2o[j >> 1][k] = Wf2[i]; }
        else       { sW1e[j >> 1][k] = Wf1[i]; sW2e[j >> 1][k] = Wf2[i]; }
    }
    for (int i = tid; i < HH * HID; i += NTHR) {          // Wf3 [15][32]
        int k = i / HID, c = i % HID; float w = Wf3[i];
        if (c & 1) sW3o[c >> 1][k] = w; else sW3e[c >> 1][k] = w;
    }
    for (int i = tid; i < HID * OUTD; i += NTHR) {        // Wl [32][8]
        int k = i / OUTD, o = i % OUTD; sWl[o][k] = Wl[i];
    }
    for (int i = tid; i < INITD * HID; i += NTHR) (&sWi[0][0])[i] = Wi[i];
    if (tid < 16) {
        sB0[tid] = (tid < HH) ? bf0[tid] : 0.f;
        sB1[tid] = (tid < HH) ? bf1[tid] : 0.f;
        sB2[tid] = (tid < HH) ? bf2[tid] : 0.f;
    }
    if (tid < HID)  sB3[tid] = bf3[tid];
    if (tid < OUTD) sBl[tid] = bl[tid];
    for (int t = tid; t < TT - 1; t += NTHR) sDt[t] = times[t + 1] - times[t];
    __syncthreads();

    // ---- mapping: 8 consecutive lanes = one batch element ----
    const int e = blockIdx.x * EPB + (tid >> 3);
    const int r = tid & 7;                     // role 0..7
    const unsigned FULL = 0xffffffffu;

    // ---- h0 = initial @ Wi + bi (replicated across the 8 roles), kept packed ----
    u64 hp[16];
    {
        float x[INITD];
#pragma unroll
        for (int k = 0; k < INITD; k++) x[k] = initial[e * INITD + k];
#pragma unroll
        for (int j = 0; j < 16; j++) {
            float a = bi[2 * j], b = bi[2 * j + 1];
#pragma unroll
            for (int k = 0; k < INITD; k++) {
                a = fmaf(x[k], sWi[k][2 * j],     a);
                b = fmaf(x[k], sWi[k][2 * j + 1], b);
            }
            hp[j] = pack2(a, b);
        }
    }

    float* __restrict__ oute = out + (size_t)e * TT * OUTD;
    const float b0e = sB0[2 * r], b0o = sB0[2 * r + 1];
    const float b1e = sB1[2 * r], b1o = sB1[2 * r + 1];
    const float b2e = sB2[2 * r], b2o = sB2[2 * r + 1];
    const float b3a = sB3[2 * r],      b3b = sB3[2 * r + 1];
    const float b3c = sB3[2 * r + 16], b3d = sB3[2 * r + 17];
    const float blr = sBl[r];

    // projection: role r writes output column o = r
    oute[r] = dot32p(&sWl[r][0], hp, blr);

    for (int t = 0; t < TT - 1; t++) {
        const float dt = sDt[t];
        const u64 dt2 = pack2(dt, dt);

        // ---- layer 0: 32 -> 16, role r owns rows 2r and 2r+1 ----
        float a0 = ftanh(dot32p(&sW0e[r][0], hp, b0e));
        float a1 = ftanh(dot32p(&sW0o[r][0], hp, b0o));
        u64 zp[8];
        u64 pl = pack2(a0, a1);                     // {z_2r, z_2r+1}
#pragma unroll
        for (int j = 0; j < 8; j++) zp[j] = __shfl_sync(FULL, pl, j, 8);

        // ---- layer 1: 16 -> 16 ----
        a0 = ftanh(dot16p(&sW1e[r][0], zp, b1e));
        a1 = ftanh(dot16p(&sW1o[r][0], zp, b1o));
        pl = pack2(a0, a1);
#pragma unroll
        for (int j = 0; j < 8; j++) zp[j] = __shfl_sync(FULL, pl, j, 8);

        // ---- layer 2: 16 -> 16 ----
        a0 = ftanh(dot16p(&sW2e[r][0], zp, b2e));
        a1 = ftanh(dot16p(&sW2o[r][0], zp, b2o));
        pl = pack2(a0, a1);
#pragma unroll
        for (int j = 0; j < 8; j++) zp[j] = __shfl_sync(FULL, pl, j, 8);

        // ---- layer 3: 16 -> 32, role r owns rows 2r,2r+1,2r+16,2r+17 ----
        float f0 = dot16p(&sW3e[r][0],     zp, b3a);
        float f1 = dot16p(&sW3o[r][0],     zp, b3b);
        float f2 = dot16p(&sW3e[r + 8][0], zp, b3c);
        float f3 = dot16p(&sW3o[r + 8][0], zp, b3d);
        const u64 fp0 = pack2(f0, f1);              // {f_2r,    f_2r+1}
        const u64 fp1 = pack2(f2, f3);              // {f_2r+16, f_2r+17}

        // ---- h += dt * f (packed pairwise all-gather) ----
#pragma unroll
        for (int j = 0; j < 8; j++) {
            hp[j]     = fma2(__shfl_sync(FULL, fp0, j, 8), dt2, hp[j]);
            hp[j + 8] = fma2(__shfl_sync(FULL, fp1, j, 8), dt2, hp[j + 8]);
        }

        // ---- projection at t+1 ----
        oute[(size_t)(t + 1) * OUTD + r] = dot32p(&sWl[r][0], hp, blr);
    }
}

extern "C" void kernel_launch(void* const* d_in, const int* in_sizes, int n_in,
                              void* d_out, int out_size) {
    const float* times   = (const float*)d_in[0];
    const float* initial = (const float*)d_in[1];
    const float* Wi  = (const float*)d_in[2];
    const float* bi  = (const float*)d_in[3];
    const float* Wf0 = (const float*)d_in[4];
    const float* bf0 = (const float*)d_in[5];
    const float* Wf1 = (const float*)d_in[6];
    const float* bf1 = (const float*)d_in[7];
    const float* Wf2 = (const float*)d_in[8];
    const float* bf2 = (const float*)d_in[9];
    const float* Wf3 = (const float*)d_in[10];
    const float* bf3 = (const float*)d_in[11];
    const float* Wl  = (const float*)d_in[12];
    const float* bl  = (const float*)d_in[13];
    float* out = (float*)d_out;

    node_kernel<<<NBLK, NTHR>>>(times, initial, Wi, bi,
                                Wf0, bf0, Wf1, bf1, Wf2, bf2, Wf3, bf3,
                                Wl, bl, out);
}

// round 9
// speedup vs baseline: 1.4567x; 1.0006x over previous
#include <cuda_runtime.h>

// Problem constants (fixed by the dataset)
#define BATCH  4096
#define TT     1000
#define HID    32
#define HH     15    // padded to 16
#define OUTD   8
#define INITD  16

#define NTHR   128                    // threads per block
#define EPB    (NTHR / 8)             // 16 elements per block (8 threads/element)
#define NBLK   (BATCH / EPB)          // 256 blocks -> 1024 warps ~ 2/SMSP

typedef unsigned long long u64;

__device__ __forceinline__ u64 pack2(float x, float y) {
    u64 r; asm("mov.b64 %0, {%1,%2};" : "=l"(r) : "f"(x), "f"(y)); return r;
}
__device__ __forceinline__ float2 unpack2(u64 v) {
    float2 p; asm("mov.b64 {%0,%1}, %2;" : "=f"(p.x), "=f"(p.y) : "l"(v)); return p;
}
// Packed f32x2 FMA / ADD (sm_100+; ptxas will not auto-fuse these)
__device__ __forceinline__ u64 fma2(u64 a, u64 b, u64 c) {
    u64 d; asm("fma.rn.f32x2 %0, %1, %2, %3;" : "=l"(d) : "l"(a), "l"(b), "l"(c)); return d;
}
__device__ __forceinline__ u64 add2(u64 a, u64 b) {
    u64 d; asm("add.rn.f32x2 %0, %1, %2;" : "=l"(d) : "l"(a), "l"(b)); return d;
}

__device__ __forceinline__ float ftanh(float x) {
    x = fminf(fmaxf(x, -15.f), 15.f);
    float e = __expf(2.f * x);
    return __fdividef(e - 1.f, e + 1.f);
}

// dot over 32 inputs: v = 16 packed k-pairs, weights = contiguous 32-float row
__device__ __forceinline__ float dot32p(const float* __restrict__ row,
                                        const u64 (&v)[16], float bias) {
    u64 acc0 = pack2(bias, 0.f);
    u64 acc1 = pack2(0.f, 0.f);
#pragma unroll
    for (int kk = 0; kk < 8; kk++) {
        ulonglong2 w = *(const ulonglong2*)(row + 4 * kk);  // 4 floats = 2 k-pairs
        acc0 = fma2(v[2 * kk + 0], w.x, acc0);
        acc1 = fma2(v[2 * kk + 1], w.y, acc1);
    }
    float2 s = unpack2(add2(acc0, acc1));
    return s.x + s.y;
}

// dot over 16 inputs: v = 8 packed k-pairs, weights = contiguous 16-float row
__device__ __forceinline__ float dot16p(const float* __restrict__ row,
                                        const u64 (&v)[8], float bias) {
    u64 acc0 = pack2(bias, 0.f);
    u64 acc1 = pack2(0.f, 0.f);
#pragma unroll
    for (int kk = 0; kk < 4; kk++) {
        ulonglong2 w = *(const ulonglong2*)(row + 4 * kk);
        acc0 = fma2(v[2 * kk + 0], w.x, acc0);
        acc1 = fma2(v[2 * kk + 1], w.y, acc1);
    }
    float2 s = unpack2(add2(acc0, acc1));
    return s.x + s.y;
}

__global__ void __launch_bounds__(NTHR) node_kernel(
    const float* __restrict__ times, const float* __restrict__ initial,
    const float* __restrict__ Wi,  const float* __restrict__ bi,
    const float* __restrict__ Wf0, const float* __restrict__ bf0,
    const float* __restrict__ Wf1, const float* __restrict__ bf1,
    const float* __restrict__ Wf2, const float* __restrict__ bf2,
    const float* __restrict__ Wf3, const float* __restrict__ bf3,
    const float* __restrict__ Wl,  const float* __restrict__ bl,
    float* __restrict__ out)
{
    // Transposed weights, even/odd output rows in separate arrays.
    // Row strides (in floats): 36 (144B) and 20 (80B) ->
    //   lanes r=0..7 read base + r*stride: offsets mod 128B are all distinct
    //   (144: {0,16,..,112}; 80: {0,80,32,112,64,16,96,48}) -> conflict-free LDS.128.
    __shared__ __align__(16) float sW0e[8][36],  sW0o[8][36];   // rows 2r / 2r+1, k<32
    __shared__ __align__(16) float sW1e[8][20],  sW1o[8][20];   // k<16 (15 + pad)
    __shared__ __align__(16) float sW2e[8][20],  sW2o[8][20];
    __shared__ __align__(16) float sW3e[16][20], sW3o[16][20];  // rows 2c / 2c+1, c<16
    __shared__ __align__(16) float sWl[8][36];                  // [o][k], k<32
    __shared__ __align__(16) float sWi[INITD][HID];
    __shared__ float sB0[16], sB1[16], sB2[16], sB3[HID], sBl[OUTD];
    __shared__ float sDt[TT - 1];

    const int tid = threadIdx.x;

    // ---- zero the padded arrays that get loaded (pads must read 0) ----
    for (int i = tid; i < 8 * 36; i += NTHR) { (&sW0e[0][0])[i] = 0.f; (&sW0o[0][0])[i] = 0.f; }
    for (int i = tid; i < 8 * 20; i += NTHR) {
        (&sW1e[0][0])[i] = 0.f; (&sW1o[0][0])[i] = 0.f;
        (&sW2e[0][0])[i] = 0.f; (&sW2o[0][0])[i] = 0.f;
    }
    for (int i = tid; i < 16 * 20; i += NTHR) { (&sW3e[0][0])[i] = 0.f; (&sW3o[0][0])[i] = 0.f; }
    __syncthreads();

    // ---- fill transposed weights ----
    for (int i = tid; i < HID * HH; i += NTHR) {          // Wf0 [32][15]
        int k = i / HH, j = i % HH; float w = Wf0[i];
        if (j & 1) sW0o[j >> 1][k] = w; else sW0e[j >> 1][k] = w;
    }
    for (int i = tid; i < HH * HH; i += NTHR) {           // Wf1/Wf2 [15][15]
        int k = i / HH, j = i % HH;
        if (j & 1) { sW1o[j >> 1][k] = Wf1[i]; sW2o[j >> 1][k] = Wf2[i]; }
        else       { sW1e[j >> 1][k] = Wf1[i]; sW2e[j >> 1][k] = Wf2[i]; }
    }
    for (int i = tid; i < HH * HID; i += NTHR) {          // Wf3 [15][32]
        int k = i / HID, c = i % HID; float w = Wf3[i];
        if (c & 1) sW3o[c >> 1][k] = w; else sW3e[c >> 1][k] = w;
    }
    for (int i = tid; i < HID * OUTD; i += NTHR) {        // Wl [32][8]
        int k = i / OUTD, o = i % OUTD; sWl[o][k] = Wl[i];
    }
    for (int i = tid; i < INITD * HID; i += NTHR) (&sWi[0][0])[i] = Wi[i];
    if (tid < 16) {
        sB0[tid] = (tid < HH) ? bf0[tid] : 0.f;
        sB1[tid] = (tid < HH) ? bf1[tid] : 0.f;
        sB2[tid] = (tid < HH) ? bf2[tid] : 0.f;
    }
    if (tid < HID)  sB3[tid] = bf3[tid];
    if (tid < OUTD) sBl[tid] = bl[tid];
    for (int t = tid; t < TT - 1; t += NTHR) sDt[t] = times[t + 1] - times[t];
    __syncthreads();

    // ---- mapping: 8 consecutive lanes = one batch element ----
    const int e = blockIdx.x * EPB + (tid >> 3);
    const int r = tid & 7;                     // role 0..7
    const unsigned FULL = 0xffffffffu;

    // ---- h0 = initial @ Wi + bi (replicated across the 8 roles), kept packed ----
    u64 hp[16];
    {
        float x[INITD];
#pragma unroll
        for (int k = 0; k < INITD; k++) x[k] = initial[e * INITD + k];
#pragma unroll
        for (int j = 0; j < 16; j++) {
            float a = bi[2 * j], b = bi[2 * j + 1];
#pragma unroll
            for (int k = 0; k < INITD; k++) {
                a = fmaf(x[k], sWi[k][2 * j],     a);
                b = fmaf(x[k], sWi[k][2 * j + 1], b);
            }
            hp[j] = pack2(a, b);
        }
    }

    float* __restrict__ oute = out + (size_t)e * TT * OUTD;
    const float b0e = sB0[2 * r], b0o = sB0[2 * r + 1];
    const float b1e = sB1[2 * r], b1o = sB1[2 * r + 1];
    const float b2e = sB2[2 * r], b2o = sB2[2 * r + 1];
    const float b3a = sB3[2 * r],      b3b = sB3[2 * r + 1];
    const float b3c = sB3[2 * r + 16], b3d = sB3[2 * r + 17];
    const float blr = sBl[r];

    // projection: role r writes output column o = r
    oute[r] = dot32p(&sWl[r][0], hp, blr);

    for (int t = 0; t < TT - 1; t++) {
        const float dt = sDt[t];
        const u64 dt2 = pack2(dt, dt);

        // ---- layer 0: 32 -> 16, role r owns rows 2r and 2r+1 ----
        float a0 = ftanh(dot32p(&sW0e[r][0], hp, b0e));
        float a1 = ftanh(dot32p(&sW0o[r][0], hp, b0o));
        u64 zp[8];
        u64 pl = pack2(a0, a1);                     // {z_2r, z_2r+1}
#pragma unroll
        for (int j = 0; j < 8; j++) zp[j] = __shfl_sync(FULL, pl, j, 8);

        // ---- layer 1: 16 -> 16 ----
        a0 = ftanh(dot16p(&sW1e[r][0], zp, b1e));
        a1 = ftanh(dot16p(&sW1o[r][0], zp, b1o));
        pl = pack2(a0, a1);
#pragma unroll
        for (int j = 0; j < 8; j++) zp[j] = __shfl_sync(FULL, pl, j, 8);

        // ---- layer 2: 16 -> 16 ----
        a0 = ftanh(dot16p(&sW2e[r][0], zp, b2e));
        a1 = ftanh(dot16p(&sW2o[r][0], zp, b2o));
        pl = pack2(a0, a1);
#pragma unroll
        for (int j = 0; j < 8; j++) zp[j] = __shfl_sync(FULL, pl, j, 8);

        // ---- layer 3: 16 -> 32, role r owns rows 2r,2r+1,2r+16,2r+17 ----
        float f0 = dot16p(&sW3e[r][0],     zp, b3a);
        float f1 = dot16p(&sW3o[r][0],     zp, b3b);
        float f2 = dot16p(&sW3e[r + 8][0], zp, b3c);
        float f3 = dot16p(&sW3o[r + 8][0], zp, b3d);
        const u64 fp0 = pack2(f0, f1);              // {f_2r,    f_2r+1}
        const u64 fp1 = pack2(f2, f3);              // {f_2r+16, f_2r+17}

        // ---- h += dt * f (packed pairwise all-gather) ----
#pragma unroll
        for (int j = 0; j < 8; j++) {
            hp[j]     = fma2(__shfl_sync(FULL, fp0, j, 8), dt2, hp[j]);
            hp[j + 8] = fma2(__shfl_sync(FULL, fp1, j, 8), dt2, hp[j + 8]);
        }

        // ---- projection at t+1 ----
        oute[(size_t)(t + 1) * OUTD + r] = dot32p(&sWl[r][0], hp, blr);
    }
}

extern "C" void kernel_launch(void* const* d_in, const int* in_sizes, int n_in,
                              void* d_out, int out_size) {
    const float* times   = (const float*)d_in[0];
    const float* initial = (const float*)d_in[1];
    const float* Wi  = (const float*)d_in[2];
    const float* bi  = (const float*)d_in[3];
    const float* Wf0 = (const float*)d_in[4];
    const float* bf0 = (const float*)d_in[5];
    const float* Wf1 = (const float*)d_in[6];
    const float* bf1 = (const float*)d_in[7];
    const float* Wf2 = (const float*)d_in[8];
    const float* bf2 = (const float*)d_in[9];
    const float* Wf3 = (const float*)d_in[10];
    const float* bf3 = (const float*)d_in[11];
    const float* Wl  = (const float*)d_in[12];
    const float* bl  = (const float*)d_in[13];
    float* out = (float*)d_out;

    node_kernel<<<NBLK, NTHR>>>(times, initial, Wi, bi,
                                Wf0, bf0, Wf1, bf1, Wf2, bf2, Wf3, bf3,
                                Wl, bl, out);
}

// round 10
// speedup vs baseline: 1.4592x; 1.0017x over previous
#include <cuda_runtime.h>

// Problem constants (fixed by the dataset)
#define BATCH  4096
#define TT     1000
#define HID    32
#define HH     15    // padded to 16
#define OUTD   8
#define INITD  16

#define NTHR   128                    // threads per block
#define EPB    (NTHR / 8)             // 16 elements per block (8 threads/element)
#define NBLK   (BATCH / EPB)          // 256 blocks -> 1024 warps ~ 2/SMSP

typedef unsigned long long u64;

__device__ __forceinline__ u64 pack2(float x, float y) {
    u64 r; asm("mov.b64 %0, {%1,%2};" : "=l"(r) : "f"(x), "f"(y)); return r;
}
__device__ __forceinline__ float2 unpack2(u64 v) {
    float2 p; asm("mov.b64 {%0,%1}, %2;" : "=f"(p.x), "=f"(p.y) : "l"(v)); return p;
}
// Packed f32x2 FMA / ADD (sm_100+; ptxas will not auto-fuse these)
__device__ __forceinline__ u64 fma2(u64 a, u64 b, u64 c) {
    u64 d; asm("fma.rn.f32x2 %0, %1, %2, %3;" : "=l"(d) : "l"(a), "l"(b), "l"(c)); return d;
}
__device__ __forceinline__ u64 add2(u64 a, u64 b) {
    u64 d; asm("add.rn.f32x2 %0, %1, %2;" : "=l"(d) : "l"(a), "l"(b)); return d;
}

__device__ __forceinline__ float ftanh(float x) {
    x = fminf(fmaxf(x, -15.f), 15.f);
    float e = __expf(2.f * x);
    return __fdividef(e - 1.f, e + 1.f);
}

// dot over 32 inputs: v = 16 packed k-pairs, weights = contiguous 32-float row
__device__ __forceinline__ float dot32p(const float* __restrict__ row,
                                        const u64 (&v)[16], float bias) {
    u64 acc0 = pack2(bias, 0.f);
    u64 acc1 = pack2(0.f, 0.f);
#pragma unroll
    for (int kk = 0; kk < 8; kk++) {
        ulonglong2 w = *(const ulonglong2*)(row + 4 * kk);  // 4 floats = 2 k-pairs
        acc0 = fma2(v[2 * kk + 0], w.x, acc0);
        acc1 = fma2(v[2 * kk + 1], w.y, acc1);
    }
    float2 s = unpack2(add2(acc0, acc1));
    return s.x + s.y;
}

// dot over 16 inputs: v = 8 packed k-pairs, weights = contiguous 16-float row
__device__ __forceinline__ float dot16p(const float* __restrict__ row,
                                        const u64 (&v)[8], float bias) {
    u64 acc0 = pack2(bias, 0.f);
    u64 acc1 = pack2(0.f, 0.f);
#pragma unroll
    for (int kk = 0; kk < 4; kk++) {
        ulonglong2 w = *(const ulonglong2*)(row + 4 * kk);
        acc0 = fma2(v[2 * kk + 0], w.x, acc0);
        acc1 = fma2(v[2 * kk + 1], w.y, acc1);
    }
    float2 s = unpack2(add2(acc0, acc1));
    return s.x + s.y;
}

__global__ void __launch_bounds__(NTHR) node_kernel(
    const float* __restrict__ times, const float* __restrict__ initial,
    const float* __restrict__ Wi,  const float* __restrict__ bi,
    const float* __restrict__ Wf0, const float* __restrict__ bf0,
    const float* __restrict__ Wf1, const float* __restrict__ bf1,
    const float* __restrict__ Wf2, const float* __restrict__ bf2,
    const float* __restrict__ Wf3, const float* __restrict__ bf3,
    const float* __restrict__ Wl,  const float* __restrict__ bl,
    float* __restrict__ out)
{
    // Transposed weights, even/odd output rows in separate arrays.
    // Row strides (in floats): 36 (144B) and 20 (80B) ->
    //   lanes r=0..7 read base + r*stride: offsets mod 128B are all distinct
    //   (144: {0,16,..,112}; 80: {0,80,32,112,64,16,96,48}) -> conflict-free LDS.128.
    __shared__ __align__(16) float sW0e[8][36],  sW0o[8][36];   // rows 2r / 2r+1, k<32
    __shared__ __align__(16) float sW1e[8][20],  sW1o[8][20];   // k<16 (15 + pad)
    __shared__ __align__(16) float sW2e[8][20],  sW2o[8][20];
    __shared__ __align__(16) float sW3e[16][20], sW3o[16][20];  // rows 2c / 2c+1, c<16
    __shared__ __align__(16) float sWl[8][36];                  // [o][k], k<32
    __shared__ __align__(16) float sWi[INITD][HID];
    __shared__ float sB0[16], sB1[16], sB2[16], sB3[HID], sBl[OUTD];
    __shared__ float sDt[TT - 1];

    const int tid = threadIdx.x;

    // ---- zero the padded arrays that get loaded (pads must read 0) ----
    for (int i = tid; i < 8 * 36; i += NTHR) { (&sW0e[0][0])[i] = 0.f; (&sW0o[0][0])[i] = 0.f; }
    for (int i = tid; i < 8 * 20; i += NTHR) {
        (&sW1e[0][0])[i] = 0.f; (&sW1o[0][0])[i] = 0.f;
        (&sW2e[0][0])[i] = 0.f; (&sW2o[0][0])[i] = 0.f;
    }
    for (int i = tid; i < 16 * 20; i += NTHR) { (&sW3e[0][0])[i] = 0.f; (&sW3o[0][0])[i] = 0.f; }
    __syncthreads();

    // ---- fill transposed weights ----
    for (int i = tid; i < HID * HH; i += NTHR) {          // Wf0 [32][15]
        int k = i / HH, j = i % HH; float w = Wf0[i];
        if (j & 1) sW0o[j >> 1][k] = w; else sW0e[j >> 1][k] = w;
    }
    for (int i = tid; i < HH * HH; i += NTHR) {           // Wf1/Wf2 [15][15]
        int k = i / HH, j = i % HH;
        if (j & 1) { sW1o[j >> 1][k] = Wf1[i]; sW2o[j >> 1][k] = Wf2[i]; }
        else       { sW1e[j >> 1][k] = Wf1[i]; sW2e[j >> 1][k] = Wf2[i]; }
    }
    for (int i = tid; i < HH * HID; i += NTHR) {          // Wf3 [15][32]
        int k = i / HID, c = i % HID; float w = Wf3[i];
        if (c & 1) sW3o[c >> 1][k] = w; else sW3e[c >> 1][k] = w;
    }
    for (int i = tid; i < HID * OUTD; i += NTHR) {        // Wl [32][8]
        int k = i / OUTD, o = i % OUTD; sWl[o][k] = Wl[i];
    }
    for (int i = tid; i < INITD * HID; i += NTHR) (&sWi[0][0])[i] = Wi[i];
    if (tid < 16) {
        sB0[tid] = (tid < HH) ? bf0[tid] : 0.f;
        sB1[tid] = (tid < HH) ? bf1[tid] : 0.f;
        sB2[tid] = (tid < HH) ? bf2[tid] : 0.f;
    }
    if (tid < HID)  sB3[tid] = bf3[tid];
    if (tid < OUTD) sBl[tid] = bl[tid];
    for (int t = tid; t < TT - 1; t += NTHR) sDt[t] = times[t + 1] - times[t];
    __syncthreads();

    // ---- mapping: 8 consecutive lanes = one batch element ----
    const int e = blockIdx.x * EPB + (tid >> 3);
    const int r = tid & 7;                     // role 0..7
    const unsigned FULL = 0xffffffffu;

    // ---- h0 = initial @ Wi + bi (replicated across the 8 roles), kept packed ----
    u64 hp[16];
    {
        float x[INITD];
#pragma unroll
        for (int k = 0; k < INITD; k++) x[k] = initial[e * INITD + k];
#pragma unroll
        for (int j = 0; j < 16; j++) {
            float a = bi[2 * j], b = bi[2 * j + 1];
#pragma unroll
            for (int k = 0; k < INITD; k++) {
                a = fmaf(x[k], sWi[k][2 * j],     a);
                b = fmaf(x[k], sWi[k][2 * j + 1], b);
            }
            hp[j] = pack2(a, b);
        }
    }

    float* __restrict__ oute = out + (size_t)e * TT * OUTD;
    const float b0e = sB0[2 * r], b0o = sB0[2 * r + 1];
    const float b1e = sB1[2 * r], b1o = sB1[2 * r + 1];
    const float b2e = sB2[2 * r], b2o = sB2[2 * r + 1];
    const float b3a = sB3[2 * r],      b3b = sB3[2 * r + 1];
    const float b3c = sB3[2 * r + 16], b3d = sB3[2 * r + 17];
    const float blr = sBl[r];

    // projection: role r writes output column o = r
    oute[r] = dot32p(&sWl[r][0], hp, blr);

    for (int t = 0; t < TT - 1; t++) {
        const float dt = sDt[t];
        const u64 dt2 = pack2(dt, dt);

        // ---- layer 0: 32 -> 16, role r owns rows 2r and 2r+1 ----
        float a0 = ftanh(dot32p(&sW0e[r][0], hp, b0e));
        float a1 = ftanh(dot32p(&sW0o[r][0], hp, b0o));
        u64 zp[8];
        u64 pl = pack2(a0, a1);                     // {z_2r, z_2r+1}
#pragma unroll
        for (int j = 0; j < 8; j++) zp[j] = __shfl_sync(FULL, pl, j, 8);

        // ---- layer 1: 16 -> 16 ----
        a0 = ftanh(dot16p(&sW1e[r][0], zp, b1e));
        a1 = ftanh(dot16p(&sW1o[r][0], zp, b1o));
        pl = pack2(a0, a1);
#pragma unroll
        for (int j = 0; j < 8; j++) zp[j] = __shfl_sync(FULL, pl, j, 8);

        // ---- layer 2: 16 -> 16 ----
        a0 = ftanh(dot16p(&sW2e[r][0], zp, b2e));
        a1 = ftanh(dot16p(&sW2o[r][0], zp, b2o));
        pl = pack2(a0, a1);
#pragma unroll
        for (int j = 0; j < 8; j++) zp[j] = __shfl_sync(FULL, pl, j, 8);

        // ---- layer 3: 16 -> 32, role r owns rows 2r,2r+1,2r+16,2r+17 ----
        float f0 = dot16p(&sW3e[r][0],     zp, b3a);
        float f1 = dot16p(&sW3o[r][0],     zp, b3b);
        float f2 = dot16p(&sW3e[r + 8][0], zp, b3c);
        float f3 = dot16p(&sW3o[r + 8][0], zp, b3d);
        const u64 fp0 = pack2(f0, f1);              // {f_2r,    f_2r+1}
        const u64 fp1 = pack2(f2, f3);              // {f_2r+16, f_2r+17}

        // ---- h += dt * f (packed pairwise all-gather) ----
#pragma unroll
        for (int j = 0; j < 8; j++) {
            hp[j]     = fma2(__shfl_sync(FULL, fp0, j, 8), dt2, hp[j]);
            hp[j + 8] = fma2(__shfl_sync(FULL, fp1, j, 8), dt2, hp[j + 8]);
        }

        // ---- projection at t+1 ----
        oute[(size_t)(t + 1) * OUTD + r] = dot32p(&sWl[r][0], hp, blr);
    }
}

extern "C" void kernel_launch(void* const* d_in, const int* in_sizes, int n_in,
                              void* d_out, int out_size) {
    const float* times   = (const float*)d_in[0];
    const float* initial = (const float*)d_in[1];
    const float* Wi  = (const float*)d_in[2];
    const float* bi  = (const float*)d_in[3];
    const float* Wf0 = (const float*)d_in[4];
    const float* bf0 = (const float*)d_in[5];
    const float* Wf1 = (const float*)d_in[6];
    const float* bf1 = (const float*)d_in[7];
    const float* Wf2 = (const float*)d_in[8];
    const float* bf2 = (const float*)d_in[9];
    const float* Wf3 = (const float*)d_in[10];
    const float* bf3 = (const float*)d_in[11];
    const float* Wl  = (const float*)d_in[12];
    const float* bl  = (const float*)d_in[13];
    float* out = (float*)d_out;

    node_kernel<<<NBLK, NTHR>>>(times, initial, Wi, bi,
                                Wf0, bf0, Wf1, bf1, Wf2, bf2, Wf3, bf3,
                                Wl, bl, out);
}